// round 2
// baseline (speedup 1.0000x reference)
#include <cuda_runtime.h>
#include <math.h>

#define TSEQ   71
#define DMODEL 1024
#define NB     1024
#define NLAYER 12
#define EPS    1e-5f

constexpr size_t BT = (size_t)NB * TSEQ;     // 72704

// ---------------- scratch (device globals; no allocs allowed) ----------------
__device__ float g_x[BT * DMODEL];           // activations       [BT, D]
__device__ float g_qkv[3 * BT * DMODEL];     // q | k | v         [3, BT, D]
__device__ float g_h[BT * 2 * DMODEL];       // FF hidden         [BT, 2D]
__device__ float g_t1[BT * DMODEL];          // attn out / FF out [BT, D]

// ---------------- helpers ----------------
__device__ __forceinline__ float2 block_sum2(float a, float b) {
    #pragma unroll
    for (int o = 16; o; o >>= 1) {
        a += __shfl_xor_sync(0xffffffffu, a, o);
        b += __shfl_xor_sync(0xffffffffu, b, o);
    }
    __shared__ float sa[8], sb[8];
    int w = threadIdx.x >> 5;
    __syncthreads();
    if ((threadIdx.x & 31) == 0) { sa[w] = a; sb[w] = b; }
    __syncthreads();
    float ta = 0.f, tb = 0.f;
    #pragma unroll
    for (int i = 0; i < 8; i++) { ta += sa[i]; tb += sb[i]; }
    return make_float2(ta, tb);
}

__device__ __forceinline__ float lrelu(float x) { return x > 0.f ? x : 0.2f * x; }

// ---------------- embedding + LN ----------------
__global__ __launch_bounds__(256) void embed_ln_kernel(
    const int* __restrict__ fen, const int* __restrict__ mv,
    const float* __restrict__ rank_emb, const float* __restrict__ file_emb,
    const float* __restrict__ fen_emb, const float* __restrict__ move_emb,
    const float* __restrict__ lng, const float* __restrict__ lnb)
{
    const int bt = blockIdx.x;
    const int b = bt / TSEQ;
    const int t = bt - b * TSEQ;
    const int d0 = threadIdx.x * 4;
    float4 v;
    if (t < 64) {
        const int r = t >> 3, f = t & 7;
        const int i1 = fen[b * 133 + t];
        const int i2 = fen[b * 133 + 64 + t];
        float4 e1 = *(const float4*)(fen_emb + (size_t)i1 * DMODEL + d0);
        float4 e2 = *(const float4*)(fen_emb + (size_t)i2 * DMODEL + d0);
        float4 re = *(const float4*)(rank_emb + (size_t)r * DMODEL + d0);
        float4 fe = *(const float4*)(file_emb + (size_t)f * DMODEL + d0);
        v.x = 0.5f * (e1.x + e2.x + re.x + fe.x);
        v.y = 0.5f * (e1.y + e2.y + re.y + fe.y);
        v.z = 0.5f * (e1.z + e2.z + re.z + fe.z);
        v.w = 0.5f * (e1.w + e2.w + re.w + fe.w);
    } else if (t < 69) {
        const int i1 = fen[b * 133 + 64 + t];   // fen cols 128..132
        v = *(const float4*)(fen_emb + (size_t)i1 * DMODEL + d0);
    } else {
        const int j = t - 69;
        const int p = mv[b * 2 + j];            // 0..63
        const int r = p >> 3, f = p & 7;
        float4 re = *(const float4*)(rank_emb + (size_t)r * DMODEL + d0);
        float4 fe = *(const float4*)(file_emb + (size_t)f * DMODEL + d0);
        float4 me = *(const float4*)(move_emb + (size_t)j * DMODEL + d0);
        v.x = 0.58f * (re.x + fe.x + me.x);
        v.y = 0.58f * (re.y + fe.y + me.y);
        v.z = 0.58f * (re.z + fe.z + me.z);
        v.w = 0.58f * (re.w + fe.w + me.w);
    }
    float s  = v.x + v.y + v.z + v.w;
    float sq = fmaf(v.x, v.x, fmaf(v.y, v.y, fmaf(v.z, v.z, v.w * v.w)));
    float2 tot = block_sum2(s, sq);
    const float mean = tot.x * (1.0f / DMODEL);
    const float var  = tot.y * (1.0f / DMODEL) - mean * mean;
    const float rstd = rsqrtf(var + EPS);
    float4 gg = ((const float4*)lng)[threadIdx.x];
    float4 bb = ((const float4*)lnb)[threadIdx.x];
    float4 o;
    o.x = (v.x - mean) * rstd * gg.x + bb.x;
    o.y = (v.y - mean) * rstd * gg.y + bb.y;
    o.z = (v.z - mean) * rstd * gg.z + bb.z;
    o.w = (v.w - mean) * rstd * gg.w + bb.w;
    *((float4*)(g_x + (size_t)bt * DMODEL) + threadIdx.x) = o;
}

// ---------------- row layernorm (in/out may alias) ----------------
__global__ __launch_bounds__(256) void ln_kernel(
    float* __restrict__ dst, const float* __restrict__ src,
    const float* __restrict__ lng, const float* __restrict__ lnb)
{
    const size_t row = blockIdx.x;
    float4 v = ((const float4*)(src + row * DMODEL))[threadIdx.x];
    float s  = v.x + v.y + v.z + v.w;
    float sq = fmaf(v.x, v.x, fmaf(v.y, v.y, fmaf(v.z, v.z, v.w * v.w)));
    float2 tot = block_sum2(s, sq);
    const float mean = tot.x * (1.0f / DMODEL);
    const float var  = tot.y * (1.0f / DMODEL) - mean * mean;
    const float rstd = rsqrtf(var + EPS);
    float4 gg = ((const float4*)lng)[threadIdx.x];
    float4 bb = ((const float4*)lnb)[threadIdx.x];
    float4 o;
    o.x = (v.x - mean) * rstd * gg.x + bb.x;
    o.y = (v.y - mean) * rstd * gg.y + bb.y;
    o.z = (v.z - mean) * rstd * gg.z + bb.z;
    o.w = (v.w - mean) * rstd * gg.w + bb.w;
    ((float4*)(dst + row * DMODEL))[threadIdx.x] = o;
}

// x = 0.7 * (x + LN(src))
__global__ __launch_bounds__(256) void ln_residual_kernel(
    float* __restrict__ x, const float* __restrict__ src,
    const float* __restrict__ lng, const float* __restrict__ lnb)
{
    const size_t row = blockIdx.x;
    float4 v = ((const float4*)(src + row * DMODEL))[threadIdx.x];
    float s  = v.x + v.y + v.z + v.w;
    float sq = fmaf(v.x, v.x, fmaf(v.y, v.y, fmaf(v.z, v.z, v.w * v.w)));
    float2 tot = block_sum2(s, sq);
    const float mean = tot.x * (1.0f / DMODEL);
    const float var  = tot.y * (1.0f / DMODEL) - mean * mean;
    const float rstd = rsqrtf(var + EPS);
    float4 gg = ((const float4*)lng)[threadIdx.x];
    float4 bb = ((const float4*)lnb)[threadIdx.x];
    float4 xv = ((const float4*)(x + row * DMODEL))[threadIdx.x];
    float4 o;
    o.x = 0.7f * (xv.x + (v.x - mean) * rstd * gg.x + bb.x);
    o.y = 0.7f * (xv.y + (v.y - mean) * rstd * gg.y + bb.y);
    o.z = 0.7f * (xv.z + (v.z - mean) * rstd * gg.z + bb.z);
    o.w = 0.7f * (xv.w + (v.w - mean) * rstd * gg.w + bb.w);
    ((float4*)(x + row * DMODEL))[threadIdx.x] = o;
}

// ---------------- GEMM: C[M,N] = A[M,K] * B ----------------
// TRANSB=false: B is [K,N] row-major.  TRANSB=true: B is [N,K] row-major (torch Linear weight).
template <bool TRANSB, bool LEAKY>
__global__ __launch_bounds__(256) void gemm_kernel(
    float* __restrict__ C, const float* __restrict__ A, const float* __restrict__ B,
    int M, int N, int K)
{
    __shared__ __align__(16) float As[8][128];
    __shared__ __align__(16) float Bs[8][128];
    const int tid  = threadIdx.x;
    const int bm   = blockIdx.y * 128;
    const int bn   = blockIdx.x * 128;
    const int lrow = tid >> 1;           // 0..127
    const int lk4  = (tid & 1) * 4;      // 0 or 4
    const int bk   = tid >> 5;           // 0..7
    const int bn4  = (tid & 31) * 4;     // 0..124
    const int ty   = tid >> 4;           // 0..15
    const int tx   = tid & 15;           // 0..15

    float acc[8][8];
    #pragma unroll
    for (int i = 0; i < 8; i++)
        #pragma unroll
        for (int j = 0; j < 8; j++) acc[i][j] = 0.f;

    const float* Ap = A + (size_t)(bm + lrow) * K + lk4;

    for (int k0 = 0; k0 < K; k0 += 8) {
        float4 av = *(const float4*)(Ap + k0);
        As[lk4 + 0][lrow] = av.x;
        As[lk4 + 1][lrow] = av.y;
        As[lk4 + 2][lrow] = av.z;
        As[lk4 + 3][lrow] = av.w;
        if (TRANSB) {
            float4 bv = *(const float4*)(B + (size_t)(bn + lrow) * K + k0 + lk4);
            Bs[lk4 + 0][lrow] = bv.x;
            Bs[lk4 + 1][lrow] = bv.y;
            Bs[lk4 + 2][lrow] = bv.z;
            Bs[lk4 + 3][lrow] = bv.w;
        } else {
            float4 bv = *(const float4*)(B + (size_t)(k0 + bk) * N + bn + bn4);
            *(float4*)&Bs[bk][bn4] = bv;
        }
        __syncthreads();
        #pragma unroll
        for (int kk = 0; kk < 8; kk++) {
            float a0[8], b0[8];
            *(float4*)&a0[0] = *(const float4*)&As[kk][ty * 8];
            *(float4*)&a0[4] = *(const float4*)&As[kk][ty * 8 + 4];
            *(float4*)&b0[0] = *(const float4*)&Bs[kk][tx * 8];
            *(float4*)&b0[4] = *(const float4*)&Bs[kk][tx * 8 + 4];
            #pragma unroll
            for (int i = 0; i < 8; i++)
                #pragma unroll
                for (int j = 0; j < 8; j++)
                    acc[i][j] = fmaf(a0[i], b0[j], acc[i][j]);
        }
        __syncthreads();
    }

    #pragma unroll
    for (int i = 0; i < 8; i++) {
        float* cr = C + (size_t)(bm + ty * 8 + i) * N + (bn + tx * 8);
        float4 r0, r1;
        if (LEAKY) {
            r0.x = lrelu(acc[i][0]); r0.y = lrelu(acc[i][1]);
            r0.z = lrelu(acc[i][2]); r0.w = lrelu(acc[i][3]);
            r1.x = lrelu(acc[i][4]); r1.y = lrelu(acc[i][5]);
            r1.z = lrelu(acc[i][6]); r1.w = lrelu(acc[i][7]);
        } else {
            r0.x = acc[i][0]; r0.y = acc[i][1]; r0.z = acc[i][2]; r0.w = acc[i][3];
            r1.x = acc[i][4]; r1.y = acc[i][5]; r1.z = acc[i][6]; r1.w = acc[i][7];
        }
        *(float4*)cr       = r0;
        *(float4*)(cr + 4) = r1;
    }
}

// ---------------- attention: one block per (b,t) row ----------------
__global__ __launch_bounds__(256) void attention_kernel(
    float* __restrict__ out, const float* __restrict__ q,
    const float* __restrict__ k, const float* __restrict__ v)
{
    __shared__ __align__(16) float qs[DMODEL];
    __shared__ float sc[TSEQ + 1];
    const int bt = blockIdx.x;
    const int b  = bt / TSEQ;
    const int tid = threadIdx.x;

    ((float4*)qs)[tid] = ((const float4*)(q + (size_t)bt * DMODEL))[tid];
    __syncthreads();

    const int warp = tid >> 5, lane = tid & 31;
    for (int s = warp; s < TSEQ; s += 8) {
        const float* krow = k + ((size_t)b * TSEQ + s) * DMODEL;
        float sum = 0.f;
        #pragma unroll 4
        for (int d = lane; d < DMODEL; d += 32) sum = fmaf(qs[d], krow[d], sum);
        #pragma unroll
        for (int o = 16; o; o >>= 1) sum += __shfl_xor_sync(0xffffffffu, sum, o);
        if (lane == 0) sc[s] = sum * 0.03125f;    // 1/sqrt(1024)
    }
    __syncthreads();

    float mx = -1e30f;
    for (int s = 0; s < TSEQ; s++) mx = fmaxf(mx, sc[s]);
    float e = 0.f;
    if (tid < TSEQ) e = expf(sc[tid] - mx);
    __syncthreads();
    if (tid < TSEQ) sc[tid] = e;
    __syncthreads();
    float ssum = 0.f;
    for (int s = 0; s < TSEQ; s++) ssum += sc[s];
    const float inv = 1.0f / ssum;

    const float* vb = v + (size_t)b * TSEQ * DMODEL;
    for (int dd = tid; dd < DMODEL; dd += 256) {
        float o = 0.f;
        for (int s = 0; s < TSEQ; s++)
            o = fmaf(sc[s], vb[(size_t)s * DMODEL + dd], o);
        out[(size_t)bt * DMODEL + dd] = o * inv;
    }
}

// ---------------- output head ----------------
__global__ __launch_bounds__(256) void head_kernel(
    float* __restrict__ out, const float* __restrict__ ow, const float* __restrict__ ob)
{
    const int b = blockIdx.x;
    const float* xr = g_x + ((size_t)b * TSEQ + 69) * DMODEL;   // tokens 69,70 contiguous
    float s = 0.f;
    for (int i = threadIdx.x; i < 2 * DMODEL; i += 256) s = fmaf(xr[i], ow[i], s);
    float2 tot = block_sum2(s, 0.f);
    if (threadIdx.x == 0)
        out[b] = 1.0f / (1.0f + expf(-(tot.x + ob[0])));
}

// ---------------- launch ----------------
extern "C" void kernel_launch(void* const* d_in, const int* in_sizes, int n_in,
                              void* d_out, int out_size)
{
    const int*   fen       = (const int*)  d_in[0];
    const int*   mv        = (const int*)  d_in[1];
    const float* rank_emb  = (const float*)d_in[2];
    const float* file_emb  = (const float*)d_in[3];
    const float* fen_emb   = (const float*)d_in[4];
    const float* move_emb  = (const float*)d_in[5];
    const float* ln_emb_g  = (const float*)d_in[6];
    const float* ln_emb_b  = (const float*)d_in[7];
    const float* qkv       = (const float*)d_in[8];
    const float* ln_q_g    = (const float*)d_in[9];
    const float* ln_q_b    = (const float*)d_in[10];
    const float* ln_k_g    = (const float*)d_in[11];
    const float* ln_k_b    = (const float*)d_in[12];
    const float* ln_attn_g = (const float*)d_in[13];
    const float* ln_attn_b = (const float*)d_in[14];
    const float* lin1      = (const float*)d_in[15];
    const float* lin2      = (const float*)d_in[16];
    const float* ln_ff_g   = (const float*)d_in[17];
    const float* ln_ff_b   = (const float*)d_in[18];
    const float* out_w     = (const float*)d_in[19];
    const float* out_b     = (const float*)d_in[20];
    float* out = (float*)d_out;

    float *px, *pqkv, *ph, *pt1;
    cudaGetSymbolAddress((void**)&px,   g_x);
    cudaGetSymbolAddress((void**)&pqkv, g_qkv);
    cudaGetSymbolAddress((void**)&ph,   g_h);
    cudaGetSymbolAddress((void**)&pt1,  g_t1);

    const unsigned nbt = (unsigned)BT;
    const size_t DD = (size_t)DMODEL * DMODEL;

    embed_ln_kernel<<<nbt, 256>>>(fen, mv, rank_emb, file_emb, fen_emb, move_emb,
                                  ln_emb_g, ln_emb_b);

    for (int i = 0; i < NLAYER; i++) {
        // y[n] = x @ qkv[i][n]   (B is [K=D, N=D] row-major -> non-transposed)
        {
            dim3 grid(DMODEL / 128, (unsigned)(BT / 128)), blk(256);
            for (int n = 0; n < 3; n++)
                gemm_kernel<false, false><<<grid, blk>>>(
                    pqkv + (size_t)n * BT * DMODEL, px,
                    qkv + ((size_t)i * 3 + n) * DD,
                    (int)BT, DMODEL, DMODEL);
        }
        // q,k layernorm in place; v untouched
        ln_kernel<<<nbt, 256>>>(pqkv, pqkv, ln_q_g + (size_t)i * DMODEL, ln_q_b + (size_t)i * DMODEL);
        ln_kernel<<<nbt, 256>>>(pqkv + BT * DMODEL, pqkv + BT * DMODEL,
                                ln_k_g + (size_t)i * DMODEL, ln_k_b + (size_t)i * DMODEL);
        // attention -> t1
        attention_kernel<<<nbt, 256>>>(pt1, pqkv, pqkv + BT * DMODEL, pqkv + 2 * BT * DMODEL);
        // x = 0.7*(x + LN(attn))
        ln_residual_kernel<<<nbt, 256>>>(px, pt1,
                                         ln_attn_g + (size_t)i * DMODEL, ln_attn_b + (size_t)i * DMODEL);
        // h = leaky(x @ lin1^T): lin1 is [2D, D] -> transposed B, N=2D, K=D
        {
            dim3 grid(2 * DMODEL / 128, (unsigned)(BT / 128)), blk(256);
            gemm_kernel<true, true><<<grid, blk>>>(
                ph, px, lin1 + (size_t)i * 2 * DD, (int)BT, 2 * DMODEL, DMODEL);
        }
        // t1 = leaky(h @ lin2^T): lin2 is [D, 2D] -> transposed B, N=D, K=2D
        {
            dim3 grid(DMODEL / 128, (unsigned)(BT / 128)), blk(256);
            gemm_kernel<true, true><<<grid, blk>>>(
                pt1, ph, lin2 + (size_t)i * 2 * DD, (int)BT, DMODEL, 2 * DMODEL);
        }
        // x = 0.7*(x + LN(ff))
        ln_residual_kernel<<<nbt, 256>>>(px, pt1,
                                         ln_ff_g + (size_t)i * DMODEL, ln_ff_b + (size_t)i * DMODEL);
    }

    head_kernel<<<NB, 256>>>(out, out_w, out_b);

    (void)in_sizes; (void)n_in; (void)out_size;
}

// round 10
// speedup vs baseline: 2.5909x; 2.5909x over previous
#include <cuda_runtime.h>
#include <math.h>
#include <stdint.h>

#define TSEQ   71
#define DMODEL 1024
#define NB     1024
#define NLAYER 12
#define EPS    1e-5f

constexpr size_t BT = (size_t)NB * TSEQ;     // 72704
constexpr size_t DD = (size_t)DMODEL * DMODEL;

// ---------------- scratch (device globals; no allocs allowed) ----------------
__device__ float g_x[BT * DMODEL];                 // activations       [BT, D]
__device__ float g_qkv[3 * BT * DMODEL];           // q | k | v         [3, BT, D]
__device__ float g_h[BT * 2 * DMODEL];             // FF hidden         [BT, 2D]
__device__ float g_t1[BT * DMODEL];                // attn out / FF out [BT, D]
__device__ float g_wqkvT[(size_t)NLAYER * 3 * DD]; // qkv weights, transposed [N,K], tf32-rna
__device__ float g_lin1r[(size_t)NLAYER * 2 * DD]; // lin1 [2D,D] tf32-rna
__device__ float g_lin2r[(size_t)NLAYER * 2 * DD]; // lin2 [D,2D] tf32-rna

// ---------------- small helpers ----------------
__device__ __forceinline__ float2 block_sum2(float a, float b) {
    #pragma unroll
    for (int o = 16; o; o >>= 1) {
        a += __shfl_xor_sync(0xffffffffu, a, o);
        b += __shfl_xor_sync(0xffffffffu, b, o);
    }
    __shared__ float sa[8], sb[8];
    int w = threadIdx.x >> 5;
    __syncthreads();
    if ((threadIdx.x & 31) == 0) { sa[w] = a; sb[w] = b; }
    __syncthreads();
    float ta = 0.f, tb = 0.f;
    #pragma unroll
    for (int i = 0; i < 8; i++) { ta += sa[i]; tb += sb[i]; }
    return make_float2(ta, tb);
}

__device__ __forceinline__ float lrelu(float x) { return x > 0.f ? x : 0.2f * x; }

__device__ __forceinline__ float rna_tf32(float x) {
    uint32_t u;
    asm("cvt.rna.tf32.f32 %0, %1;" : "=r"(u) : "f"(x));
    return __uint_as_float(u);
}
__device__ __forceinline__ uint32_t rna_tf32_u(float x) {
    uint32_t u;
    asm("cvt.rna.tf32.f32 %0, %1;" : "=r"(u) : "f"(x));
    return u;
}

__device__ __forceinline__ uint32_t smem_u32(const void* p) {
    uint32_t a;
    asm("{ .reg .u64 t; cvta.to.shared.u64 t, %1; cvt.u32.u64 %0, t; }" : "=r"(a) : "l"(p));
    return a;
}

__device__ __forceinline__ void cp16(uint32_t dst, const void* src) {
    asm volatile("cp.async.cg.shared.global [%0], [%1], 16;\n" :: "r"(dst), "l"(src));
}

// ---------------- tf32 mma.sync GEMM ----------------
// C[M,N] = act(A[M,K] @ Bw^T), Bw is [N,K] row-major (K-major per N-row).
// BM=128 BN=128 BK=32, 256 thr / 8 warps (2x4), warp tile 64x32, m16n8k8.
#define GBK 32
constexpr int GROWF   = GBK + 4;        // 36 floats per smem row (conflict-free, 16B aligned)
constexpr int GTILEF  = 128 * GROWF;    // 4608 floats per tile
constexpr int GSTAGEF = 2 * GTILEF;     // A+B per stage
constexpr int GSMEM_BYTES = 2 * GSTAGEF * 4;   // 73728

__device__ __forceinline__ void mma_tf32(float* c, const uint32_t* a, const uint32_t* b) {
    asm volatile(
        "mma.sync.aligned.m16n8k8.row.col.f32.tf32.tf32.f32 "
        "{%0,%1,%2,%3}, {%4,%5,%6,%7}, {%8,%9}, {%0,%1,%2,%3};"
        : "+f"(c[0]), "+f"(c[1]), "+f"(c[2]), "+f"(c[3])
        : "r"(a[0]), "r"(a[1]), "r"(a[2]), "r"(a[3]), "r"(b[0]), "r"(b[1]));
}

template <bool LEAKY>
__global__ __launch_bounds__(256) void gemm_mma(
    float* __restrict__ C, const float* __restrict__ A, const float* __restrict__ Bw,
    int N, int K)
{
    extern __shared__ float sm[];
    const int tid  = threadIdx.x;
    const int lane = tid & 31;
    const int wid  = tid >> 5;
    const int bm = blockIdx.y * 128;
    const int bn = blockIdx.x * 128;
    const int m0 = (wid >> 2) * 64;
    const int n0 = (wid & 3) * 32;
    const int gid = lane >> 2;
    const int tig = lane & 3;

    const float* Ab = A  + (size_t)bm * K;
    const float* Bb = Bw + (size_t)bn * K;

    auto load_chunk = [&](int ch) {
        float* dA = sm + (ch & 1) * GSTAGEF;
        float* dB = dA + GTILEF;
        const float* gA = Ab + ch * GBK;
        const float* gB = Bb + ch * GBK;
        #pragma unroll
        for (int i = 0; i < 4; i++) {
            const int idx = i * 256 + tid;
            const int r = idx >> 3, c = idx & 7;
            cp16(smem_u32(dA + r * GROWF + c * 4), gA + (size_t)r * K + c * 4);
        }
        #pragma unroll
        for (int i = 0; i < 4; i++) {
            const int idx = i * 256 + tid;
            const int r = idx >> 3, c = idx & 7;
            cp16(smem_u32(dB + r * GROWF + c * 4), gB + (size_t)r * K + c * 4);
        }
        asm volatile("cp.async.commit_group;\n" ::: "memory");
    };

    float acc[4][4][4];
    #pragma unroll
    for (int mt = 0; mt < 4; mt++)
        #pragma unroll
        for (int nt = 0; nt < 4; nt++)
            #pragma unroll
            for (int v = 0; v < 4; v++) acc[mt][nt][v] = 0.f;

    const int nch = K / GBK;
    load_chunk(0);
    load_chunk(1);

    for (int ch = 0; ch < nch; ch++) {
        if (ch + 1 < nch) asm volatile("cp.async.wait_group 1;\n" ::: "memory");
        else              asm volatile("cp.async.wait_group 0;\n" ::: "memory");
        __syncthreads();
        const float* sA = sm + (ch & 1) * GSTAGEF;
        const float* sB = sA + GTILEF;

        #pragma unroll
        for (int kk = 0; kk < 4; kk++) {
            uint32_t af[4][4], bf[4][2];
            #pragma unroll
            for (int mt = 0; mt < 4; mt++) {
                const float* p = sA + (m0 + mt * 16 + gid) * GROWF + kk * 8 + tig;
                af[mt][0] = rna_tf32_u(p[0]);
                af[mt][1] = rna_tf32_u(p[8 * GROWF]);
                af[mt][2] = rna_tf32_u(p[4]);
                af[mt][3] = rna_tf32_u(p[8 * GROWF + 4]);
            }
            #pragma unroll
            for (int nt = 0; nt < 4; nt++) {
                const float* p = sB + (n0 + nt * 8 + gid) * GROWF + kk * 8 + tig;
                bf[nt][0] = __float_as_uint(p[0]);
                bf[nt][1] = __float_as_uint(p[4]);
            }
            #pragma unroll
            for (int mt = 0; mt < 4; mt++)
                #pragma unroll
                for (int nt = 0; nt < 4; nt++)
                    mma_tf32(acc[mt][nt], af[mt], bf[nt]);
        }
        __syncthreads();
        if (ch + 2 < nch) load_chunk(ch + 2);
    }

    // epilogue: direct float2 stores per fragment
    #pragma unroll
    for (int mt = 0; mt < 4; mt++) {
        #pragma unroll
        for (int nt = 0; nt < 4; nt++) {
            const int r0 = bm + m0 + mt * 16 + gid;
            const int c0 = bn + n0 + nt * 8 + tig * 2;
            float v0 = acc[mt][nt][0], v1 = acc[mt][nt][1];
            float v2 = acc[mt][nt][2], v3 = acc[mt][nt][3];
            if (LEAKY) { v0 = lrelu(v0); v1 = lrelu(v1); v2 = lrelu(v2); v3 = lrelu(v3); }
            *(float2*)(C + (size_t)r0 * N + c0)       = make_float2(v0, v1);
            *(float2*)(C + (size_t)(r0 + 8) * N + c0) = make_float2(v2, v3);
        }
    }
}

// ---------------- weight prep ----------------
__global__ __launch_bounds__(256) void wprep_transpose_kernel(
    float* __restrict__ out, const float* __restrict__ in)   // 1024x1024 per blockIdx.z
{
    __shared__ float t[32][33];
    const float* src = in  + (size_t)blockIdx.z * DD;
    float*       dst = out + (size_t)blockIdx.z * DD;
    const int x  = blockIdx.x * 32 + threadIdx.x;
    const int y0 = blockIdx.y * 32;
    #pragma unroll
    for (int i = threadIdx.y; i < 32; i += 8)
        t[i][threadIdx.x] = src[(size_t)(y0 + i) * DMODEL + x];
    __syncthreads();
    const int ox  = blockIdx.y * 32 + threadIdx.x;
    const int oy0 = blockIdx.x * 32;
    #pragma unroll
    for (int i = threadIdx.y; i < 32; i += 8)
        dst[(size_t)(oy0 + i) * DMODEL + ox] = rna_tf32(t[threadIdx.x][i]);
}

__global__ __launch_bounds__(256) void wprep_round_kernel(
    float* __restrict__ out, const float* __restrict__ in, size_t n)
{
    size_t i = (size_t)blockIdx.x * 256 + threadIdx.x;
    size_t stride = (size_t)gridDim.x * 256;
    for (; i < n; i += stride) out[i] = rna_tf32(in[i]);
}

// ---------------- embedding + LN ----------------
__global__ __launch_bounds__(256) void embed_ln_kernel(
    const int* __restrict__ fen, const int* __restrict__ mv,
    const float* __restrict__ rank_emb, const float* __restrict__ file_emb,
    const float* __restrict__ fen_emb, const float* __restrict__ move_emb,
    const float* __restrict__ lng, const float* __restrict__ lnb)
{
    const int bt = blockIdx.x;
    const int b = bt / TSEQ;
    const int t = bt - b * TSEQ;
    const int d0 = threadIdx.x * 4;
    float4 v;
    if (t < 64) {
        const int r = t >> 3, f = t & 7;
        const int i1 = fen[b * 133 + t];
        const int i2 = fen[b * 133 + 64 + t];
        float4 e1 = *(const float4*)(fen_emb + (size_t)i1 * DMODEL + d0);
        float4 e2 = *(const float4*)(fen_emb + (size_t)i2 * DMODEL + d0);
        float4 re = *(const float4*)(rank_emb + (size_t)r * DMODEL + d0);
        float4 fe = *(const float4*)(file_emb + (size_t)f * DMODEL + d0);
        v.x = 0.5f * (e1.x + e2.x + re.x + fe.x);
        v.y = 0.5f * (e1.y + e2.y + re.y + fe.y);
        v.z = 0.5f * (e1.z + e2.z + re.z + fe.z);
        v.w = 0.5f * (e1.w + e2.w + re.w + fe.w);
    } else if (t < 69) {
        const int i1 = fen[b * 133 + 64 + t];
        v = *(const float4*)(fen_emb + (size_t)i1 * DMODEL + d0);
    } else {
        const int j = t - 69;
        const int p = mv[b * 2 + j];
        const int r = p >> 3, f = p & 7;
        float4 re = *(const float4*)(rank_emb + (size_t)r * DMODEL + d0);
        float4 fe = *(const float4*)(file_emb + (size_t)f * DMODEL + d0);
        float4 me = *(const float4*)(move_emb + (size_t)j * DMODEL + d0);
        v.x = 0.58f * (re.x + fe.x + me.x);
        v.y = 0.58f * (re.y + fe.y + me.y);
        v.z = 0.58f * (re.z + fe.z + me.z);
        v.w = 0.58f * (re.w + fe.w + me.w);
    }
    float s  = v.x + v.y + v.z + v.w;
    float sq = fmaf(v.x, v.x, fmaf(v.y, v.y, fmaf(v.z, v.z, v.w * v.w)));
    float2 tot = block_sum2(s, sq);
    const float mean = tot.x * (1.0f / DMODEL);
    const float var  = tot.y * (1.0f / DMODEL) - mean * mean;
    const float rstd = rsqrtf(var + EPS);
    float4 gg = ((const float4*)lng)[threadIdx.x];
    float4 bb = ((const float4*)lnb)[threadIdx.x];
    float4 o;
    o.x = (v.x - mean) * rstd * gg.x + bb.x;
    o.y = (v.y - mean) * rstd * gg.y + bb.y;
    o.z = (v.z - mean) * rstd * gg.z + bb.z;
    o.w = (v.w - mean) * rstd * gg.w + bb.w;
    *((float4*)(g_x + (size_t)bt * DMODEL) + threadIdx.x) = o;
}

// ---------------- row layernorm ----------------
__global__ __launch_bounds__(256) void ln_kernel(
    float* __restrict__ dst, const float* __restrict__ src,
    const float* __restrict__ lng, const float* __restrict__ lnb)
{
    const size_t row = blockIdx.x;
    float4 v = ((const float4*)(src + row * DMODEL))[threadIdx.x];
    float s  = v.x + v.y + v.z + v.w;
    float sq = fmaf(v.x, v.x, fmaf(v.y, v.y, fmaf(v.z, v.z, v.w * v.w)));
    float2 tot = block_sum2(s, sq);
    const float mean = tot.x * (1.0f / DMODEL);
    const float var  = tot.y * (1.0f / DMODEL) - mean * mean;
    const float rstd = rsqrtf(var + EPS);
    float4 gg = ((const float4*)lng)[threadIdx.x];
    float4 bb = ((const float4*)lnb)[threadIdx.x];
    float4 o;
    o.x = (v.x - mean) * rstd * gg.x + bb.x;
    o.y = (v.y - mean) * rstd * gg.y + bb.y;
    o.z = (v.z - mean) * rstd * gg.z + bb.z;
    o.w = (v.w - mean) * rstd * gg.w + bb.w;
    ((float4*)(dst + row * DMODEL))[threadIdx.x] = o;
}

// x = 0.7 * (x + LN(src))
__global__ __launch_bounds__(256) void ln_residual_kernel(
    float* __restrict__ x, const float* __restrict__ src,
    const float* __restrict__ lng, const float* __restrict__ lnb)
{
    const size_t row = blockIdx.x;
    float4 v = ((const float4*)(src + row * DMODEL))[threadIdx.x];
    float s  = v.x + v.y + v.z + v.w;
    float sq = fmaf(v.x, v.x, fmaf(v.y, v.y, fmaf(v.z, v.z, v.w * v.w)));
    float2 tot = block_sum2(s, sq);
    const float mean = tot.x * (1.0f / DMODEL);
    const float var  = tot.y * (1.0f / DMODEL) - mean * mean;
    const float rstd = rsqrtf(var + EPS);
    float4 gg = ((const float4*)lng)[threadIdx.x];
    float4 bb = ((const float4*)lnb)[threadIdx.x];
    float4 xv = ((const float4*)(x + row * DMODEL))[threadIdx.x];
    float4 o;
    o.x = 0.7f * (xv.x + (v.x - mean) * rstd * gg.x + bb.x);
    o.y = 0.7f * (xv.y + (v.y - mean) * rstd * gg.y + bb.y);
    o.z = 0.7f * (xv.z + (v.z - mean) * rstd * gg.z + bb.z);
    o.w = 0.7f * (xv.w + (v.w - mean) * rstd * gg.w + bb.w);
    ((float4*)(x + row * DMODEL))[threadIdx.x] = o;
}

// ---------------- attention: one block per (b,t) row ----------------
__global__ __launch_bounds__(256) void attention_kernel(
    float* __restrict__ out, const float* __restrict__ q,
    const float* __restrict__ k, const float* __restrict__ v)
{
    __shared__ __align__(16) float qs[DMODEL];
    __shared__ float sc[TSEQ + 1];
    const int bt = blockIdx.x;
    const int b  = bt / TSEQ;
    const int tid = threadIdx.x;

    ((float4*)qs)[tid] = ((const float4*)(q + (size_t)bt * DMODEL))[tid];
    __syncthreads();

    const int warp = tid >> 5, lane = tid & 31;
    for (int s = warp; s < TSEQ; s += 8) {
        const float* krow = k + ((size_t)b * TSEQ + s) * DMODEL;
        float sum = 0.f;
        #pragma unroll 4
        for (int d = lane; d < DMODEL; d += 32) sum = fmaf(qs[d], krow[d], sum);
        #pragma unroll
        for (int o = 16; o; o >>= 1) sum += __shfl_xor_sync(0xffffffffu, sum, o);
        if (lane == 0) sc[s] = sum * 0.03125f;
    }
    __syncthreads();

    float mx = -1e30f;
    for (int s = 0; s < TSEQ; s++) mx = fmaxf(mx, sc[s]);
    float e = 0.f;
    if (tid < TSEQ) e = expf(sc[tid] - mx);
    __syncthreads();
    if (tid < TSEQ) sc[tid] = e;
    __syncthreads();
    float ssum = 0.f;
    for (int s = 0; s < TSEQ; s++) ssum += sc[s];
    const float inv = 1.0f / ssum;

    const float* vb = v + (size_t)b * TSEQ * DMODEL;
    for (int dd = tid; dd < DMODEL; dd += 256) {
        float o = 0.f;
        for (int s = 0; s < TSEQ; s++)
            o = fmaf(sc[s], vb[(size_t)s * DMODEL + dd], o);
        out[(size_t)bt * DMODEL + dd] = o * inv;
    }
}

// ---------------- output head ----------------
__global__ __launch_bounds__(256) void head_kernel(
    float* __restrict__ out, const float* __restrict__ ow, const float* __restrict__ ob)
{
    const int b = blockIdx.x;
    const float* xr = g_x + ((size_t)b * TSEQ + 69) * DMODEL;
    float s = 0.f;
    for (int i = threadIdx.x; i < 2 * DMODEL; i += 256) s = fmaf(xr[i], ow[i], s);
    float2 tot = block_sum2(s, 0.f);
    if (threadIdx.x == 0)
        out[b] = 1.0f / (1.0f + expf(-(tot.x + ob[0])));
}

// ---------------- launch ----------------
extern "C" void kernel_launch(void* const* d_in, const int* in_sizes, int n_in,
                              void* d_out, int out_size)
{
    const int*   fen       = (const int*)  d_in[0];
    const int*   mv        = (const int*)  d_in[1];
    const float* rank_emb  = (const float*)d_in[2];
    const float* file_emb  = (const float*)d_in[3];
    const float* fen_emb   = (const float*)d_in[4];
    const float* move_emb  = (const float*)d_in[5];
    const float* ln_emb_g  = (const float*)d_in[6];
    const float* ln_emb_b  = (const float*)d_in[7];
    const float* qkv       = (const float*)d_in[8];
    const float* ln_q_g    = (const float*)d_in[9];
    const float* ln_q_b    = (const float*)d_in[10];
    const float* ln_k_g    = (const float*)d_in[11];
    const float* ln_k_b    = (const float*)d_in[12];
    const float* ln_attn_g = (const float*)d_in[13];
    const float* ln_attn_b = (const float*)d_in[14];
    const float* lin1      = (const float*)d_in[15];
    const float* lin2      = (const float*)d_in[16];
    const float* ln_ff_g   = (const float*)d_in[17];
    const float* ln_ff_b   = (const float*)d_in[18];
    const float* out_w     = (const float*)d_in[19];
    const float* out_b     = (const float*)d_in[20];
    float* out = (float*)d_out;

    float *px, *pqkv, *ph, *pt1, *pwq, *pl1, *pl2;
    cudaGetSymbolAddress((void**)&px,   g_x);
    cudaGetSymbolAddress((void**)&pqkv, g_qkv);
    cudaGetSymbolAddress((void**)&ph,   g_h);
    cudaGetSymbolAddress((void**)&pt1,  g_t1);
    cudaGetSymbolAddress((void**)&pwq,  g_wqkvT);
    cudaGetSymbolAddress((void**)&pl1,  g_lin1r);
    cudaGetSymbolAddress((void**)&pl2,  g_lin2r);

    cudaFuncSetAttribute(gemm_mma<false>, cudaFuncAttributeMaxDynamicSharedMemorySize, GSMEM_BYTES);
    cudaFuncSetAttribute(gemm_mma<true>,  cudaFuncAttributeMaxDynamicSharedMemorySize, GSMEM_BYTES);

    const unsigned nbt = (unsigned)BT;

    // ---- weight prep ----
    {
        dim3 g(32, 32, NLAYER * 3), blk(32, 8);
        wprep_transpose_kernel<<<g, blk>>>(pwq, qkv);
        size_t nf = (size_t)NLAYER * 2 * DD;
        wprep_round_kernel<<<2048, 256>>>(pl1, lin1, nf);
        wprep_round_kernel<<<2048, 256>>>(pl2, lin2, nf);
    }

    embed_ln_kernel<<<nbt, 256>>>(fen, mv, rank_emb, file_emb, fen_emb, move_emb,
                                  ln_emb_g, ln_emb_b);

    for (int i = 0; i < NLAYER; i++) {
        // QKV: y[n] = x @ W[n]  via W^T rows, [N=D, K=D]
        {
            dim3 grid(DMODEL / 128, (unsigned)(BT / 128)), blk(256);
            for (int n = 0; n < 3; n++)
                gemm_mma<false><<<grid, blk, GSMEM_BYTES>>>(
                    pqkv + (size_t)n * BT * DMODEL, px,
                    pwq + ((size_t)i * 3 + n) * DD, DMODEL, DMODEL);
        }
        ln_kernel<<<nbt, 256>>>(pqkv, pqkv, ln_q_g + (size_t)i * DMODEL, ln_q_b + (size_t)i * DMODEL);
        ln_kernel<<<nbt, 256>>>(pqkv + BT * DMODEL, pqkv + BT * DMODEL,
                                ln_k_g + (size_t)i * DMODEL, ln_k_b + (size_t)i * DMODEL);
        attention_kernel<<<nbt, 256>>>(pt1, pqkv, pqkv + BT * DMODEL, pqkv + 2 * BT * DMODEL);
        ln_residual_kernel<<<nbt, 256>>>(px, pt1,
                                         ln_attn_g + (size_t)i * DMODEL, ln_attn_b + (size_t)i * DMODEL);
        // FF1: h = leaky(x @ lin1^T), lin1r [N=2D, K=D]
        {
            dim3 grid(2 * DMODEL / 128, (unsigned)(BT / 128)), blk(256);
            gemm_mma<true><<<grid, blk, GSMEM_BYTES>>>(
                ph, px, pl1 + (size_t)i * 2 * DD, 2 * DMODEL, DMODEL);
        }
        // FF2: t1 = leaky(h @ lin2^T), lin2r [N=D, K=2D]
        {
            dim3 grid(DMODEL / 128, (unsigned)(BT / 128)), blk(256);
            gemm_mma<true><<<grid, blk, GSMEM_BYTES>>>(
                pt1, ph, pl2 + (size_t)i * 2 * DD, DMODEL, 2 * DMODEL);
        }
        ln_residual_kernel<<<nbt, 256>>>(px, pt1,
                                         ln_ff_g + (size_t)i * DMODEL, ln_ff_b + (size_t)i * DMODEL);
    }

    head_kernel<<<NB, 256>>>(out, out_w, out_b);

    (void)in_sizes; (void)n_in; (void)out_size;
}

// round 14
// speedup vs baseline: 3.5228x; 1.3597x over previous
#include <cuda_runtime.h>
#include <cuda_fp16.h>
#include <math.h>
#include <stdint.h>

#define TSEQ   71
#define DMODEL 1024
#define NB     1024
#define NLAYER 12
#define EPS    1e-5f

constexpr size_t BT = (size_t)NB * TSEQ;     // 72704
constexpr size_t DD = (size_t)DMODEL * DMODEL;

// ---------------- scratch (device globals; no allocs allowed) ----------------
__device__ float  g_x[BT * DMODEL];                  // activations fp32   [BT, D]
__device__ __half g_xh[BT * DMODEL];                 // fp16 copy of x (GEMM A)
__device__ float  g_qkv[3 * BT * DMODEL];            // q | k | v          [3, BT, D]
__device__ __half g_h[BT * 2 * DMODEL];              // FF hidden fp16     [BT, 2D]
__device__ float  g_t1[BT * DMODEL];                 // attn out / FF out  [BT, D]
__device__ __half g_wqkvTh[(size_t)NLAYER * 3 * DD]; // qkv W^T fp16, [3072,1024]/layer
__device__ __half g_lin1h[(size_t)NLAYER * 2 * DD];  // lin1 [2D,D] fp16
__device__ __half g_lin2h[(size_t)NLAYER * 2 * DD];  // lin2 [D,2D] fp16

// ---------------- small helpers ----------------
__device__ __forceinline__ float2 block_sum2(float a, float b) {
    #pragma unroll
    for (int o = 16; o; o >>= 1) {
        a += __shfl_xor_sync(0xffffffffu, a, o);
        b += __shfl_xor_sync(0xffffffffu, b, o);
    }
    __shared__ float sa[8], sb[8];
    int w = threadIdx.x >> 5;
    __syncthreads();
    if ((threadIdx.x & 31) == 0) { sa[w] = a; sb[w] = b; }
    __syncthreads();
    float ta = 0.f, tb = 0.f;
    #pragma unroll
    for (int i = 0; i < 8; i++) { ta += sa[i]; tb += sb[i]; }
    return make_float2(ta, tb);
}

__device__ __forceinline__ float lrelu(float x) { return x > 0.f ? x : 0.2f * x; }

__device__ __forceinline__ uint32_t smem_u32(const void* p) {
    uint32_t a;
    asm("{ .reg .u64 t; cvta.to.shared.u64 t, %1; cvt.u32.u64 %0, t; }" : "=r"(a) : "l"(p));
    return a;
}

__device__ __forceinline__ void cp16(uint32_t dst, const void* src) {
    asm volatile("cp.async.cg.shared.global [%0], [%1], 16;\n" :: "r"(dst), "l"(src));
}

__device__ __forceinline__ void mma_f16(float* c, const uint32_t* a, const uint32_t* b) {
    asm volatile(
        "mma.sync.aligned.m16n8k16.row.col.f32.f16.f16.f32 "
        "{%0,%1,%2,%3}, {%4,%5,%6,%7}, {%8,%9}, {%0,%1,%2,%3};"
        : "+f"(c[0]), "+f"(c[1]), "+f"(c[2]), "+f"(c[3])
        : "r"(a[0]), "r"(a[1]), "r"(a[2]), "r"(a[3]), "r"(b[0]), "r"(b[1]));
}

// write float4 as 4 fp16 (two half2) to h-copy
__device__ __forceinline__ void store_h4(__half* dst, float4 o) {
    __half2* d2 = (__half2*)dst;
    d2[0] = __floats2half2_rn(o.x, o.y);
    d2[1] = __floats2half2_rn(o.z, o.w);
}

// ---------------- fp16 mma GEMM ----------------
// C[M,N] = act(A[M,K] @ Bw^T), A fp16 [M,K], Bw fp16 [N,K] row-major.
// CTA tile 128x256, warp tile 64x64 (8 warps, 2x4), BK=32, double-buffered cp.async.
#define GBK 32
constexpr int KROW  = 40;                      // halfs per smem row (32 + 8 pad)
constexpr int HSTG  = (128 + 256) * KROW;      // halfs per stage = 15360
constexpr int GSMEM_BYTES = 2 * HSTG * 2;      // 61440 bytes

// MODE: 0 = fp32 store, qkv split over 3 sub-tensors of N=1024 (Ntotal=3072)
//       1 = fp16 store + leaky (FF1)
//       2 = fp32 store + leaky (FF2)
template <int MODE>
__global__ __launch_bounds__(256) void gemm_h(
    void* __restrict__ Cv, const __half* __restrict__ A, const __half* __restrict__ Bw,
    int N, int K)
{
    extern __shared__ __align__(16) __half hsm[];
    const int tid  = threadIdx.x;
    const int lane = tid & 31;
    const int wid  = tid >> 5;
    const int bm = blockIdx.y * 128;
    const int bn = blockIdx.x * 256;
    const int m0 = (wid >> 2) * 64;
    const int n0 = (wid & 3) * 64;
    const int gid = lane >> 2;
    const int tig = lane & 3;

    const __half* Ab = A  + (size_t)bm * K;
    const __half* Bb = Bw + (size_t)bn * K;

    auto load_chunk = [&](int ch) {
        __half* dA = hsm + (ch & 1) * HSTG;
        __half* dB = dA + 128 * KROW;
        const __half* gA = Ab + ch * GBK;
        const __half* gB = Bb + ch * GBK;
        #pragma unroll
        for (int i = 0; i < 2; i++) {            // A: 128 rows x 4 cp16
            const int idx = i * 256 + tid;
            const int r = idx >> 2, c = idx & 3;
            cp16(smem_u32(dA + r * KROW + c * 8), gA + (size_t)r * K + c * 8);
        }
        #pragma unroll
        for (int i = 0; i < 4; i++) {            // B: 256 rows x 4 cp16
            const int idx = i * 256 + tid;
            const int r = idx >> 2, c = idx & 3;
            cp16(smem_u32(dB + r * KROW + c * 8), gB + (size_t)r * K + c * 8);
        }
        asm volatile("cp.async.commit_group;\n" ::: "memory");
    };

    float acc[4][8][4];
    #pragma unroll
    for (int mt = 0; mt < 4; mt++)
        #pragma unroll
        for (int nt = 0; nt < 8; nt++)
            #pragma unroll
            for (int v = 0; v < 4; v++) acc[mt][nt][v] = 0.f;

    const int nch = K / GBK;
    load_chunk(0);
    load_chunk(1);

    for (int ch = 0; ch < nch; ch++) {
        if (ch + 1 < nch) asm volatile("cp.async.wait_group 1;\n" ::: "memory");
        else              asm volatile("cp.async.wait_group 0;\n" ::: "memory");
        __syncthreads();
        const __half* sA = hsm + (ch & 1) * HSTG;
        const __half* sB = sA + 128 * KROW;

        #pragma unroll
        for (int ks = 0; ks < 2; ks++) {         // two m16n8k16 k-steps per 32-chunk
            const int k0 = ks * 16;
            uint32_t af[4][4], bf[8][2];
            #pragma unroll
            for (int mt = 0; mt < 4; mt++) {
                const __half* p = sA + (m0 + mt * 16 + gid) * KROW + k0 + 2 * tig;
                af[mt][0] = *(const uint32_t*)p;
                af[mt][1] = *(const uint32_t*)(p + 8 * KROW);
                af[mt][2] = *(const uint32_t*)(p + 8);
                af[mt][3] = *(const uint32_t*)(p + 8 * KROW + 8);
            }
            #pragma unroll
            for (int nt = 0; nt < 8; nt++) {
                const __half* p = sB + (n0 + nt * 8 + gid) * KROW + k0 + 2 * tig;
                bf[nt][0] = *(const uint32_t*)p;
                bf[nt][1] = *(const uint32_t*)(p + 8);
            }
            #pragma unroll
            for (int mt = 0; mt < 4; mt++)
                #pragma unroll
                for (int nt = 0; nt < 8; nt++)
                    mma_f16(acc[mt][nt], af[mt], bf[nt]);
        }
        __syncthreads();
        if (ch + 2 < nch) load_chunk(ch + 2);
    }

    // ---- epilogue ----
    float*  Cf = nullptr;
    __half* Ch = nullptr;
    int colbase = bn, Nst = N;
    if (MODE == 0) {                 // split q|k|v
        const int which = bn >> 10;
        Cf = (float*)Cv + (size_t)which * BT * DMODEL;
        colbase = bn & 1023;
        Nst = DMODEL;
    } else if (MODE == 1) {
        Ch = (__half*)Cv;
    } else {
        Cf = (float*)Cv;
    }

    #pragma unroll
    for (int mt = 0; mt < 4; mt++) {
        #pragma unroll
        for (int nt = 0; nt < 8; nt++) {
            const int r0 = bm + m0 + mt * 16 + gid;
            const int c0 = colbase + n0 + nt * 8 + tig * 2;
            float v0 = acc[mt][nt][0], v1 = acc[mt][nt][1];
            float v2 = acc[mt][nt][2], v3 = acc[mt][nt][3];
            if (MODE != 0) { v0 = lrelu(v0); v1 = lrelu(v1); v2 = lrelu(v2); v3 = lrelu(v3); }
            if (MODE == 1) {
                *(__half2*)(Ch + (size_t)r0 * Nst + c0)       = __floats2half2_rn(v0, v1);
                *(__half2*)(Ch + (size_t)(r0 + 8) * Nst + c0) = __floats2half2_rn(v2, v3);
            } else {
                *(float2*)(Cf + (size_t)r0 * Nst + c0)       = make_float2(v0, v1);
                *(float2*)(Cf + (size_t)(r0 + 8) * Nst + c0) = make_float2(v2, v3);
            }
        }
    }
}

// ---------------- weight prep ----------------
__global__ __launch_bounds__(256) void wprep_transpose_h(
    __half* __restrict__ out, const float* __restrict__ in)   // 1024x1024 per blockIdx.z
{
    __shared__ float t[32][33];
    const float* src = in  + (size_t)blockIdx.z * DD;
    __half*      dst = out + (size_t)blockIdx.z * DD;
    const int x  = blockIdx.x * 32 + threadIdx.x;
    const int y0 = blockIdx.y * 32;
    #pragma unroll
    for (int i = threadIdx.y; i < 32; i += 8)
        t[i][threadIdx.x] = src[(size_t)(y0 + i) * DMODEL + x];
    __syncthreads();
    const int ox  = blockIdx.y * 32 + threadIdx.x;
    const int oy0 = blockIdx.x * 32;
    #pragma unroll
    for (int i = threadIdx.y; i < 32; i += 8)
        dst[(size_t)(oy0 + i) * DMODEL + ox] = __float2half_rn(t[threadIdx.x][i]);
}

__global__ __launch_bounds__(256) void wprep_half_kernel(
    __half* __restrict__ out, const float* __restrict__ in, size_t n)
{
    size_t i = (size_t)blockIdx.x * 256 + threadIdx.x;
    size_t stride = (size_t)gridDim.x * 256;
    for (; i < n; i += stride) out[i] = __float2half_rn(in[i]);
}

// ---------------- embedding + LN (writes fp32 x and fp16 copy) ----------------
__global__ __launch_bounds__(256) void embed_ln_kernel(
    const int* __restrict__ fen, const int* __restrict__ mv,
    const float* __restrict__ rank_emb, const float* __restrict__ file_emb,
    const float* __restrict__ fen_emb, const float* __restrict__ move_emb,
    const float* __restrict__ lng, const float* __restrict__ lnb)
{
    const int bt = blockIdx.x;
    const int b = bt / TSEQ;
    const int t = bt - b * TSEQ;
    const int d0 = threadIdx.x * 4;
    float4 v;
    if (t < 64) {
        const int r = t >> 3, f = t & 7;
        const int i1 = fen[b * 133 + t];
        const int i2 = fen[b * 133 + 64 + t];
        float4 e1 = *(const float4*)(fen_emb + (size_t)i1 * DMODEL + d0);
        float4 e2 = *(const float4*)(fen_emb + (size_t)i2 * DMODEL + d0);
        float4 re = *(const float4*)(rank_emb + (size_t)r * DMODEL + d0);
        float4 fe = *(const float4*)(file_emb + (size_t)f * DMODEL + d0);
        v.x = 0.5f * (e1.x + e2.x + re.x + fe.x);
        v.y = 0.5f * (e1.y + e2.y + re.y + fe.y);
        v.z = 0.5f * (e1.z + e2.z + re.z + fe.z);
        v.w = 0.5f * (e1.w + e2.w + re.w + fe.w);
    } else if (t < 69) {
        const int i1 = fen[b * 133 + 64 + t];
        v = *(const float4*)(fen_emb + (size_t)i1 * DMODEL + d0);
    } else {
        const int j = t - 69;
        const int p = mv[b * 2 + j];
        const int r = p >> 3, f = p & 7;
        float4 re = *(const float4*)(rank_emb + (size_t)r * DMODEL + d0);
        float4 fe = *(const float4*)(file_emb + (size_t)f * DMODEL + d0);
        float4 me = *(const float4*)(move_emb + (size_t)j * DMODEL + d0);
        v.x = 0.58f * (re.x + fe.x + me.x);
        v.y = 0.58f * (re.y + fe.y + me.y);
        v.z = 0.58f * (re.z + fe.z + me.z);
        v.w = 0.58f * (re.w + fe.w + me.w);
    }
    float s  = v.x + v.y + v.z + v.w;
    float sq = fmaf(v.x, v.x, fmaf(v.y, v.y, fmaf(v.z, v.z, v.w * v.w)));
    float2 tot = block_sum2(s, sq);
    const float mean = tot.x * (1.0f / DMODEL);
    const float var  = tot.y * (1.0f / DMODEL) - mean * mean;
    const float rstd = rsqrtf(var + EPS);
    float4 gg = ((const float4*)lng)[threadIdx.x];
    float4 bb = ((const float4*)lnb)[threadIdx.x];
    float4 o;
    o.x = (v.x - mean) * rstd * gg.x + bb.x;
    o.y = (v.y - mean) * rstd * gg.y + bb.y;
    o.z = (v.z - mean) * rstd * gg.z + bb.z;
    o.w = (v.w - mean) * rstd * gg.w + bb.w;
    *((float4*)(g_x + (size_t)bt * DMODEL) + threadIdx.x) = o;
    store_h4(g_xh + (size_t)bt * DMODEL + d0, o);
}

// ---------------- q/k layernorm in one launch (in place, fp32) ----------------
__global__ __launch_bounds__(256) void ln_qk_kernel(
    float* __restrict__ qk,
    const float* __restrict__ gq, const float* __restrict__ bq,
    const float* __restrict__ gk, const float* __restrict__ bk)
{
    const size_t row = blockIdx.x;               // 0..2*BT-1
    const bool isq = row < BT;
    float* base = qk + row * DMODEL;
    const float* lng = isq ? gq : gk;
    const float* lnb = isq ? bq : bk;
    float4 v = ((const float4*)base)[threadIdx.x];
    float s  = v.x + v.y + v.z + v.w;
    float sq = fmaf(v.x, v.x, fmaf(v.y, v.y, fmaf(v.z, v.z, v.w * v.w)));
    float2 tot = block_sum2(s, sq);
    const float mean = tot.x * (1.0f / DMODEL);
    const float var  = tot.y * (1.0f / DMODEL) - mean * mean;
    const float rstd = rsqrtf(var + EPS);
    float4 gg = ((const float4*)lng)[threadIdx.x];
    float4 bb = ((const float4*)lnb)[threadIdx.x];
    float4 o;
    o.x = (v.x - mean) * rstd * gg.x + bb.x;
    o.y = (v.y - mean) * rstd * gg.y + bb.y;
    o.z = (v.z - mean) * rstd * gg.z + bb.z;
    o.w = (v.w - mean) * rstd * gg.w + bb.w;
    ((float4*)base)[threadIdx.x] = o;
}

// x = 0.7 * (x + LN(src)); also writes fp16 copy of new x
__global__ __launch_bounds__(256) void ln_residual_kernel(
    float* __restrict__ x, const float* __restrict__ src,
    const float* __restrict__ lng, const float* __restrict__ lnb)
{
    const size_t row = blockIdx.x;
    float4 v = ((const float4*)(src + row * DMODEL))[threadIdx.x];
    float s  = v.x + v.y + v.z + v.w;
    float sq = fmaf(v.x, v.x, fmaf(v.y, v.y, fmaf(v.z, v.z, v.w * v.w)));
    float2 tot = block_sum2(s, sq);
    const float mean = tot.x * (1.0f / DMODEL);
    const float var  = tot.y * (1.0f / DMODEL) - mean * mean;
    const float rstd = rsqrtf(var + EPS);
    float4 gg = ((const float4*)lng)[threadIdx.x];
    float4 bb = ((const float4*)lnb)[threadIdx.x];
    float4 xv = ((const float4*)(x + row * DMODEL))[threadIdx.x];
    float4 o;
    o.x = 0.7f * (xv.x + (v.x - mean) * rstd * gg.x + bb.x);
    o.y = 0.7f * (xv.y + (v.y - mean) * rstd * gg.y + bb.y);
    o.z = 0.7f * (xv.z + (v.z - mean) * rstd * gg.z + bb.z);
    o.w = 0.7f * (xv.w + (v.w - mean) * rstd * gg.w + bb.w);
    ((float4*)(x + row * DMODEL))[threadIdx.x] = o;
    store_h4(g_xh + row * DMODEL + threadIdx.x * 4, o);
}

// ---------------- attention v2: one block per batch element ----------------
// smem: Qc [80][133], Kc/Vc [80][133], scores [80][81]
constexpr int AROW = 133;
constexpr int SROW = 81;
constexpr int ATT_SMEM = (2 * 80 * AROW + 80 * SROW) * 4;   // 111,040 bytes

__global__ __launch_bounds__(256) void attention2_kernel(
    float* __restrict__ out, const float* __restrict__ q,
    const float* __restrict__ k, const float* __restrict__ v)
{
    extern __shared__ __align__(16) float fsm[];
    float* bq = fsm;
    float* bk = bq + 80 * AROW;
    float* sc = bk + 80 * AROW;

    const int b   = blockIdx.x;
    const int tid = threadIdx.x;
    const int ty  = tid >> 4;        // 0..15
    const int tx  = tid & 15;        // 0..15
    const int warp = tid >> 5, lane = tid & 31;
    const size_t rowbase = (size_t)b * TSEQ * DMODEL;

    auto load_tile = [&](float* dst, const float* src, int c) {
        #pragma unroll 5
        for (int idx = tid; idx < 80 * 32; idx += 256) {
            const int r = idx >> 5, c4 = (idx & 31) * 4;
            float4 val = make_float4(0.f, 0.f, 0.f, 0.f);
            if (r < TSEQ)
                val = *(const float4*)(src + rowbase + (size_t)r * DMODEL + c * 128 + c4);
            float* d = dst + r * AROW + c4;
            d[0] = val.x; d[1] = val.y; d[2] = val.z; d[3] = val.w;
        }
    };

    // ---- phase 1: scores (register-resident 5x5 accumulators) ----
    float acc[5][5];
    #pragma unroll
    for (int i = 0; i < 5; i++)
        #pragma unroll
        for (int j = 0; j < 5; j++) acc[i][j] = 0.f;

    for (int c = 0; c < 8; c++) {
        load_tile(bq, q, c);
        load_tile(bk, k, c);
        __syncthreads();
        #pragma unroll 4
        for (int d = 0; d < 128; d++) {
            float qa[5], ka[5];
            #pragma unroll
            for (int i = 0; i < 5; i++) qa[i] = bq[(ty * 5 + i) * AROW + d];
            #pragma unroll
            for (int j = 0; j < 5; j++) ka[j] = bk[(tx * 5 + j) * AROW + d];
            #pragma unroll
            for (int i = 0; i < 5; i++)
                #pragma unroll
                for (int j = 0; j < 5; j++)
                    acc[i][j] = fmaf(qa[i], ka[j], acc[i][j]);
        }
        __syncthreads();
    }
    #pragma unroll
    for (int i = 0; i < 5; i++)
        #pragma unroll
        for (int j = 0; j < 5; j++)
            sc[(ty * 5 + i) * SROW + tx * 5 + j] = acc[i][j] * 0.03125f;
    __syncthreads();

    // ---- softmax (warp per row); zero pad cols 71..79 ----
    for (int t = warp; t < TSEQ; t += 8) {
        float* row = sc + t * SROW;
        float m = -1e30f;
        for (int s = lane; s < TSEQ; s += 32) m = fmaxf(m, row[s]);
        #pragma unroll
        for (int o = 16; o; o >>= 1) m = fmaxf(m, __shfl_xor_sync(0xffffffffu, m, o));
        float sum = 0.f;
        for (int s = lane; s < 80; s += 32) {
            float e = (s < TSEQ) ? __expf(row[s] - m) : 0.f;
            row[s] = e; sum += e;
        }
        #pragma unroll
        for (int o = 16; o; o >>= 1) sum += __shfl_xor_sync(0xffffffffu, sum, o);
        const float inv = 1.0f / sum;
        for (int s = lane; s < 80; s += 32) row[s] *= inv;
    }
    __syncthreads();

    // ---- phase 2: AV ----
    for (int c = 0; c < 8; c++) {
        load_tile(bq, v, c);   // reuse bq for V chunk
        __syncthreads();
        float oa[5][8];
        #pragma unroll
        for (int i = 0; i < 5; i++)
            #pragma unroll
            for (int j = 0; j < 8; j++) oa[i][j] = 0.f;
        for (int s = 0; s < TSEQ; s++) {
            float pa[5], va[8];
            #pragma unroll
            for (int i = 0; i < 5; i++) pa[i] = sc[(ty * 5 + i) * SROW + s];
            #pragma unroll
            for (int j = 0; j < 8; j++) va[j] = bq[s * AROW + tx + 16 * j];
            #pragma unroll
            for (int i = 0; i < 5; i++)
                #pragma unroll
                for (int j = 0; j < 8; j++)
                    oa[i][j] = fmaf(pa[i], va[j], oa[i][j]);
        }
        #pragma unroll
        for (int i = 0; i < 5; i++) {
            const int t = ty * 5 + i;
            if (t < TSEQ) {
                float* orow = out + rowbase + (size_t)t * DMODEL + c * 128;
                #pragma unroll
                for (int j = 0; j < 8; j++) orow[tx + 16 * j] = oa[i][j];
            }
        }
        __syncthreads();
    }
}

// ---------------- output head ----------------
__global__ __launch_bounds__(256) void head_kernel(
    float* __restrict__ out, const float* __restrict__ ow, const float* __restrict__ ob)
{
    const int b = blockIdx.x;
    const float* xr = g_x + ((size_t)b * TSEQ + 69) * DMODEL;
    float s = 0.f;
    for (int i = threadIdx.x; i < 2 * DMODEL; i += 256) s = fmaf(xr[i], ow[i], s);
    float2 tot = block_sum2(s, 0.f);
    if (threadIdx.x == 0)
        out[b] = 1.0f / (1.0f + expf(-(tot.x + ob[0])));
}

// ---------------- launch ----------------
extern "C" void kernel_launch(void* const* d_in, const int* in_sizes, int n_in,
                              void* d_out, int out_size)
{
    const int*   fen       = (const int*)  d_in[0];
    const int*   mv        = (const int*)  d_in[1];
    const float* rank_emb  = (const float*)d_in[2];
    const float* file_emb  = (const float*)d_in[3];
    const float* fen_emb   = (const float*)d_in[4];
    const float* move_emb  = (const float*)d_in[5];
    const float* ln_emb_g  = (const float*)d_in[6];
    const float* ln_emb_b  = (const float*)d_in[7];
    const float* qkv       = (const float*)d_in[8];
    const float* ln_q_g    = (const float*)d_in[9];
    const float* ln_q_b    = (const float*)d_in[10];
    const float* ln_k_g    = (const float*)d_in[11];
    const float* ln_k_b    = (const float*)d_in[12];
    const float* ln_attn_g = (const float*)d_in[13];
    const float* ln_attn_b = (const float*)d_in[14];
    const float* lin1      = (const float*)d_in[15];
    const float* lin2      = (const float*)d_in[16];
    const float* ln_ff_g   = (const float*)d_in[17];
    const float* ln_ff_b   = (const float*)d_in[18];
    const float* out_w     = (const float*)d_in[19];
    const float* out_b     = (const float*)d_in[20];
    float* out = (float*)d_out;

    float *px, *pqkv, *pt1;
    __half *pxh, *ph, *pwq, *pl1, *pl2;
    cudaGetSymbolAddress((void**)&px,   g_x);
    cudaGetSymbolAddress((void**)&pxh,  g_xh);
    cudaGetSymbolAddress((void**)&pqkv, g_qkv);
    cudaGetSymbolAddress((void**)&ph,   g_h);
    cudaGetSymbolAddress((void**)&pt1,  g_t1);
    cudaGetSymbolAddress((void**)&pwq,  g_wqkvTh);
    cudaGetSymbolAddress((void**)&pl1,  g_lin1h);
    cudaGetSymbolAddress((void**)&pl2,  g_lin2h);

    cudaFuncSetAttribute(gemm_h<0>, cudaFuncAttributeMaxDynamicSharedMemorySize, GSMEM_BYTES);
    cudaFuncSetAttribute(gemm_h<1>, cudaFuncAttributeMaxDynamicSharedMemorySize, GSMEM_BYTES);
    cudaFuncSetAttribute(gemm_h<2>, cudaFuncAttributeMaxDynamicSharedMemorySize, GSMEM_BYTES);
    cudaFuncSetAttribute(attention2_kernel, cudaFuncAttributeMaxDynamicSharedMemorySize, ATT_SMEM);

    const unsigned nbt = (unsigned)BT;

    // ---- weight prep ----
    {
        dim3 g(32, 32, NLAYER * 3), blk(32, 8);
        wprep_transpose_h<<<g, blk>>>(pwq, qkv);
        size_t nf = (size_t)NLAYER * 2 * DD;
        wprep_half_kernel<<<2048, 256>>>(pl1, lin1, nf);
        wprep_half_kernel<<<2048, 256>>>(pl2, lin2, nf);
    }

    embed_ln_kernel<<<nbt, 256>>>(fen, mv, rank_emb, file_emb, fen_emb, move_emb,
                                  ln_emb_g, ln_emb_b);

    for (int i = 0; i < NLAYER; i++) {
        // QKV: single fused launch, N=3072, split epilogue
        {
            dim3 grid(3072 / 256, (unsigned)(BT / 128)), blk(256);
            gemm_h<0><<<grid, blk, GSMEM_BYTES>>>(
                pqkv, pxh, pwq + (size_t)i * 3 * DD, 3072, DMODEL);
        }
        // q,k layernorm (one launch covers both)
        ln_qk_kernel<<<2 * nbt, 256>>>(pqkv,
            ln_q_g + (size_t)i * DMODEL, ln_q_b + (size_t)i * DMODEL,
            ln_k_g + (size_t)i * DMODEL, ln_k_b + (size_t)i * DMODEL);
        // attention -> t1
        attention2_kernel<<<NB, 256, ATT_SMEM>>>(pt1, pqkv, pqkv + BT * DMODEL,
                                                 pqkv + 2 * BT * DMODEL);
        // x = 0.7*(x + LN(attn)) (+ fp16 copy)
        ln_residual_kernel<<<nbt, 256>>>(px, pt1,
                                         ln_attn_g + (size_t)i * DMODEL, ln_attn_b + (size_t)i * DMODEL);
        // FF1: h = leaky(x @ lin1^T) -> fp16
        {
            dim3 grid(2 * DMODEL / 256, (unsigned)(BT / 128)), blk(256);
            gemm_h<1><<<grid, blk, GSMEM_BYTES>>>(
                ph, pxh, pl1 + (size_t)i * 2 * DD, 2 * DMODEL, DMODEL);
        }
        // FF2: t1 = leaky(h @ lin2^T) -> fp32
        {
            dim3 grid(DMODEL / 256, (unsigned)(BT / 128)), blk(256);
            gemm_h<2><<<grid, blk, GSMEM_BYTES>>>(
                pt1, ph, pl2 + (size_t)i * 2 * DD, DMODEL, 2 * DMODEL);
        }
        // x = 0.7*(x + LN(ff)) (+ fp16 copy)
        ln_residual_kernel<<<nbt, 256>>>(px, pt1,
                                         ln_ff_g + (size_t)i * DMODEL, ln_ff_b + (size_t)i * DMODEL);
    }

    head_kernel<<<NB, 256>>>(out, out_w, out_b);

    (void)in_sizes; (void)n_in; (void)out_size;
}